// round 12
// baseline (speedup 1.0000x reference)
#include <cuda_runtime.h>
#include <cstdint>

// Dynamic per-pixel 5x5 conv (KPN) + leaky_relu(0.2), replicate padding.
// x:      (N=4, C=8, H=256, W=256) f32   -> d_in[0]
// kernel: (N=4, C*25=200, H=256, W=256)  -> d_in[1]
// out:    (N=4, C=8, H=256, W=256) f32
//
// R11: cp.async (LDGSTS) staging of the kernel stream. Depth no longer costs
// registers: each thread stages 5 float4 per tap into a private 80B smem slot,
// 3-stage ring, no CTA barriers (wait_group only; each thread reads only its
// own bytes). Thread stride 80B -> conflict-free LDS.128. ~10 LDGSTS in
// flight/warp at ~28 warps/SM. x loads stay direct LDG (L1/L2, 25x reuse).

#define NN   4
#define CC   8
#define HH   256
#define WW   256
#define KK   5
#define PAD  2
#define NEG_SLOPE 0.2f

#define W4   (WW / 4)           // 64
#define HW4  (HH * W4)          // 16384 float4 per plane
#define TOTAL_THREADS (NN * CC * HH * W4)   // 524288
#define BLOCK 128
#define SLOT  80                 // bytes per thread per stage (5 x float4)
#define STAGE_BYTES (BLOCK * SLOT)   // 10240
#define NSTAGE 3

__device__ __forceinline__ void cp16(uint32_t s, const void* g) {
    asm volatile("cp.async.cg.shared.global [%0], [%1], 16;"
                 :: "r"(s), "l"(g));
}
__device__ __forceinline__ void cp_commit() {
    asm volatile("cp.async.commit_group;" ::: "memory");
}
template <int N>
__device__ __forceinline__ void cp_wait() {
    asm volatile("cp.async.wait_group %0;" :: "n"(N) : "memory");
}
__device__ __forceinline__ float lrelu(float v) {
    return v >= 0.f ? v : NEG_SLOPE * v;
}

__global__ __launch_bounds__(BLOCK, 8) void dynconv_kernel(
    const float* __restrict__ x,
    const float* __restrict__ ker,
    float* __restrict__ out)
{
    __shared__ __align__(16) char stagebuf[NSTAGE * STAGE_BYTES];

    int tid = blockIdx.x * BLOCK + threadIdx.x;

    int w4 = tid & (W4 - 1);
    int h  = (tid >> 6) & (HH - 1);
    int nc = tid >> 14;                 // 0 .. N*C-1
    int w0 = w4 << 2;

    const float* xbase = x + (size_t)nc * (HH * WW);
    const float4* kbase = reinterpret_cast<const float4*>(ker)
                        + (size_t)nc * 25 * HW4
                        + (size_t)h * W4 + w4;

    uint32_t myslot = (uint32_t)__cvta_generic_to_shared(stagebuf)
                    + threadIdx.x * SLOT;
    char* myslot_g = stagebuf + threadIdx.x * SLOT;   // generic, for LDS reads

    // Issue staging for tap k1 into ring stage s.
    #define ISSUE(k1, s)                                                  \
        do {                                                              \
            uint32_t sb = myslot + (s) * STAGE_BYTES;                     \
            _Pragma("unroll")                                             \
            for (int k2 = 0; k2 < KK; k2++)                               \
                cp16(sb + k2 * 16, kbase + (size_t)((k1) * KK + k2) * HW4); \
            cp_commit();                                                  \
        } while (0)

    ISSUE(0, 0);
    ISSUE(1, 1);
    ISSUE(2, 2);

    float a0 = 0.f, a1 = 0.f, a2 = 0.f, a3 = 0.f;

    #define BODY(rr, WAITN)                                               \
        do {                                                              \
            /* x row for this tap (independent of staged data) */         \
            int r = h + (rr) - PAD;                                       \
            r = max(0, min(HH - 1, r));                                   \
            const float* row = xbase + r * WW;                            \
            float xv[8];                                                  \
            _Pragma("unroll")                                             \
            for (int i = 0; i < 8; i++) {                                 \
                int cidx = w0 + i - PAD;                                  \
                cidx = max(0, min(WW - 1, cidx));                         \
                xv[i] = __ldg(row + cidx);                                \
            }                                                             \
            cp_wait<WAITN>();                                             \
            const float4* kst = reinterpret_cast<const float4*>(          \
                myslot_g + ((rr) % NSTAGE) * STAGE_BYTES);                \
            _Pragma("unroll")                                             \
            for (int k2 = 0; k2 < KK; k2++) {                             \
                float4 kv = kst[k2];                                      \
                a0 = fmaf(xv[k2 + 0], kv.x, a0);                          \
                a1 = fmaf(xv[k2 + 1], kv.y, a1);                          \
                a2 = fmaf(xv[k2 + 2], kv.z, a2);                          \
                a3 = fmaf(xv[k2 + 3], kv.w, a3);                          \
            }                                                             \
        } while (0)

    // rr=0: issue tap3 first (4 groups out), wait until <=3 pending.
    ISSUE(3, 0 % NSTAGE);       // stage 0 is consumed below only AFTER wait;
                                // NOTE: tap3 must land in stage (3 % 3) = 0,
                                // but stage 0 still holds tap0! -> see below.
    // The above would clobber stage 0 before tap0 is consumed. Correct order:
    // consume tap0 first, then reuse its stage. So: undo — structured below.
    // (ISSUE above is intentionally placed before BODY(0) is WRONG; real
    //  sequence:)
    // -- restructured correct sequence --
    // We cannot "unissue"; instead stage assignment for tap3 is stage 0 and
    // we must wait for tap0 BEFORE tap3's cp.async writes stage 0. cp.async
    // writes are ordered only by wait_group, and the writes themselves come
    // from this same thread AFTER the wait below in program order? No — the
    // ISSUE(3,0) above executes before the wait. To keep it simple and
    // correct, we use 3 stages but only issue the next tap AFTER consuming
    // the stage it reuses. The ISSUE(3,...) above is therefore moved into
    // the bodies; the line above is neutralized by using a 4th pattern:
    // tap3 -> we issued into stage 0 BEFORE waiting on tap0. This is a
    // hazard. Fix: tap3 was issued into stage 0, but tap0's data in stage 0
    // is only read after cp_wait<3>() which does NOT guarantee tap3 hasn't
    // landed. => DO NOT SHIP THIS PATH.
    #undef BODY
    #undef ISSUE
    // ---- clean, hazard-free implementation (4-deep ring, issue-after-use) --
    {
        uint32_t sb0 = myslot + 0 * STAGE_BYTES;
        // re-derive: stages 0,1,2 hold taps 0,1,2 (already issued above,
        // plus a duplicate of tap3 into stage 0 which may race tap0).
        // To guarantee correctness regardless, re-issue tap0 into stage 0 and
        // drain everything first: cheap (L2 hit) and removes the hazard.
        cp_wait<0>();                          // drain all prior groups
        // stage 0 now holds tap3's data (last writer). Re-issue tap 0:
        #pragma unroll
        for (int k2 = 0; k2 < KK; k2++)
            cp16(sb0 + k2 * 16, kbase + (size_t)(0 * KK + k2) * HW4);
        cp_commit();
        cp_wait<0>();                          // tap0 ready in stage 0
    }

    // Sequential, simple pipeline from here: consume tap rr from stage rr%3,
    // then issue tap rr+3 into the freed stage (no hazard: issue after use).
    #define BODY2(rr)                                                     \
        do {                                                              \
            int r = h + (rr) - PAD;                                       \
            r = max(0, min(HH - 1, r));                                   \
            const float* row = xbase + r * WW;                            \
            float xv[8];                                                  \
            _Pragma("unroll")                                             \
            for (int i = 0; i < 8; i++) {                                 \
                int cidx = w0 + i - PAD;                                  \
                cidx = max(0, min(WW - 1, cidx));                         \
                xv[i] = __ldg(row + cidx);                                \
            }                                                             \
            cp_wait<0>();                                                 \
            const float4* kst = reinterpret_cast<const float4*>(          \
                myslot_g + ((rr) % NSTAGE) * STAGE_BYTES);                \
            float4 kq[KK];                                                \
            _Pragma("unroll")                                             \
            for (int k2 = 0; k2 < KK; k2++) kq[k2] = kst[k2];             \
            if ((rr) + NSTAGE < KK) {                                     \
                uint32_t sb = myslot + ((rr) % NSTAGE) * STAGE_BYTES;     \
                _Pragma("unroll")                                         \
                for (int k2 = 0; k2 < KK; k2++)                           \
                    cp16(sb + k2 * 16,                                    \
                         kbase + (size_t)(((rr) + NSTAGE) * KK + k2) * HW4); \
                cp_commit();                                              \
            }                                                             \
            _Pragma("unroll")                                             \
            for (int k2 = 0; k2 < KK; k2++) {                             \
                a0 = fmaf(xv[k2 + 0], kq[k2].x, a0);                      \
                a1 = fmaf(xv[k2 + 1], kq[k2].y, a1);                      \
                a2 = fmaf(xv[k2 + 2], kq[k2].z, a2);                      \
                a3 = fmaf(xv[k2 + 3], kq[k2].w, a3);                      \
            }                                                             \
        } while (0)

    BODY2(0);
    BODY2(1);
    BODY2(2);
    BODY2(3);
    BODY2(4);
    #undef BODY2

    float4 o;
    o.x = lrelu(a0); o.y = lrelu(a1); o.z = lrelu(a2); o.w = lrelu(a3);
    reinterpret_cast<float4*>(out)[tid] = o;
}

extern "C" void kernel_launch(void* const* d_in, const int* in_sizes, int n_in,
                              void* d_out, int out_size)
{
    const float* x   = (const float*)d_in[0];
    const float* ker = (const float*)d_in[1];
    float* out = (float*)d_out;

    dynconv_kernel<<<TOTAL_THREADS / BLOCK, BLOCK>>>(x, ker, out);
}

// round 15
// speedup vs baseline: 1.2548x; 1.2548x over previous
#include <cuda_runtime.h>
#include <cstdint>

// Dynamic per-pixel 5x5 conv (KPN) + leaky_relu(0.2), replicate padding.
// x:      (N=4, C=8, H=256, W=256) f32   -> d_in[0]
// kernel: (N=4, C*25=200, H=256, W=256)  -> d_in[1]
// out:    (N=4, C=8, H=256, W=256) f32
//
// R13: CLEAN cp.async staging of the kernel stream (R12 shipped a broken
// serialized variant; this is the intended pipeline). 3-stage per-thread ring
// (80B slots, conflict-free LDS.128), waits <2,2,2,1,0> keep 2-3 LDGSTS
// groups in flight per warp with zero destination registers. Issue-after-
// consume ordering, no barriers, no duplicate traffic. x loads direct LDG.

#define NN   4
#define CC   8
#define HH   256
#define WW   256
#define KK   5
#define PAD  2
#define NEG_SLOPE 0.2f

#define W4   (WW / 4)                 // 64
#define HW4  (HH * W4)                // 16384 float4 per plane
#define TOTAL_THREADS (NN * CC * HH * W4)   // 524288
#define BLOCK 128
#define SLOT  80                      // bytes per thread per stage (5 float4)
#define STAGE_BYTES (BLOCK * SLOT)    // 10240
#define NSTAGE 3                      // 30720 B smem/CTA -> 7 CTAs/SM

__device__ __forceinline__ void cp16(uint32_t s, const void* g) {
    asm volatile("cp.async.cg.shared.global [%0], [%1], 16;" :: "r"(s), "l"(g));
}
__device__ __forceinline__ void cp_commit() {
    asm volatile("cp.async.commit_group;" ::: "memory");
}
template <int N>
__device__ __forceinline__ void cp_wait() {
    asm volatile("cp.async.wait_group %0;" :: "n"(N) : "memory");
}
__device__ __forceinline__ float lrelu(float v) {
    return v >= 0.f ? v : NEG_SLOPE * v;
}

__global__ __launch_bounds__(BLOCK, 7) void dynconv_kernel(
    const float* __restrict__ x,
    const float* __restrict__ ker,
    float* __restrict__ out)
{
    __shared__ __align__(16) char stagebuf[NSTAGE * STAGE_BYTES];

    int tid = blockIdx.x * BLOCK + threadIdx.x;

    int w4 = tid & (W4 - 1);
    int h  = (tid >> 6) & (HH - 1);
    int nc = tid >> 14;                 // 0 .. N*C-1
    int w0 = w4 << 2;

    const float* xbase = x + (size_t)nc * (HH * WW);
    const float4* kbase = reinterpret_cast<const float4*>(ker)
                        + (size_t)nc * 25 * HW4
                        + (size_t)h * W4 + w4;

    uint32_t myslot = (uint32_t)__cvta_generic_to_shared(stagebuf)
                    + threadIdx.x * SLOT;
    const char* myslot_g = stagebuf + threadIdx.x * SLOT;

    // Prologue: stage taps 0,1,2 into ring stages 0,1,2 (3 commit groups).
    #pragma unroll
    for (int t = 0; t < NSTAGE; t++) {
        uint32_t sb = myslot + t * STAGE_BYTES;
        #pragma unroll
        for (int k2 = 0; k2 < KK; k2++)
            cp16(sb + k2 * 16, kbase + (size_t)(t * KK + k2) * HW4);
        cp_commit();
    }

    float a0 = 0.f, a1 = 0.f, a2 = 0.f, a3 = 0.f;

    // At consume of tap rr: issued = 3+min(rr,2) groups, need rr+1 complete
    // -> allowed pending = 2,2,2,1,0.
    #define BODY(rr, WAITN)                                                  \
        do {                                                                 \
            int r = h + (rr) - PAD;                                          \
            r = max(0, min(HH - 1, r));                                      \
            const float* row = xbase + r * WW;                               \
            float xv[8];                                                     \
            _Pragma("unroll")                                                \
            for (int i = 0; i < 8; i++) {                                    \
                int cidx = w0 + i - PAD;                                     \
                cidx = max(0, min(WW - 1, cidx));                            \
                xv[i] = __ldg(row + cidx);                                   \
            }                                                                \
            cp_wait<WAITN>();                                                \
            const float4* kst = reinterpret_cast<const float4*>(             \
                myslot_g + ((rr) % NSTAGE) * STAGE_BYTES);                   \
            float4 kq[KK];                                                   \
            _Pragma("unroll")                                                \
            for (int k2 = 0; k2 < KK; k2++) kq[k2] = kst[k2];                \
            if ((rr) + NSTAGE < KK) {  /* refill freed stage with tap rr+3 */\
                uint32_t sb = myslot + ((rr) % NSTAGE) * STAGE_BYTES;        \
                _Pragma("unroll")                                            \
                for (int k2 = 0; k2 < KK; k2++)                              \
                    cp16(sb + k2 * 16,                                       \
                         kbase + (size_t)(((rr) + NSTAGE) * KK + k2) * HW4); \
                cp_commit();                                                 \
            }                                                                \
            _Pragma("unroll")                                                \
            for (int k2 = 0; k2 < KK; k2++) {                                \
                a0 = fmaf(xv[k2 + 0], kq[k2].x, a0);                         \
                a1 = fmaf(xv[k2 + 1], kq[k2].y, a1);                         \
                a2 = fmaf(xv[k2 + 2], kq[k2].z, a2);                         \
                a3 = fmaf(xv[k2 + 3], kq[k2].w, a3);                         \
            }                                                                \
        } while (0)

    BODY(0, 2);
    BODY(1, 2);
    BODY(2, 2);
    BODY(3, 1);
    BODY(4, 0);
    #undef BODY

    float4 o;
    o.x = lrelu(a0); o.y = lrelu(a1); o.z = lrelu(a2); o.w = lrelu(a3);
    reinterpret_cast<float4*>(out)[tid] = o;
}

extern "C" void kernel_launch(void* const* d_in, const int* in_sizes, int n_in,
                              void* d_out, int out_size)
{
    const float* x   = (const float*)d_in[0];
    const float* ker = (const float*)d_in[1];
    float* out = (float*)d_out;

    dynconv_kernel<<<TOTAL_THREADS / BLOCK, BLOCK>>>(x, ker, out);
}